// round 2
// baseline (speedup 1.0000x reference)
#include <cuda_runtime.h>
#include <cuda_fp16.h>
#include <math.h>

// Problem constants
#define B_      256
#define L_      16
#define U_      512
#define T_STEPS 256
#define NT      16      // N tiles (512 / 32)
#define MT      4       // M tiles (256 / 64)
#define N_TILE  32
#define M_TILE  64
#define NCTA    64
#define WT_STRIDE 1032  // padded row stride (halfs) for bank-conflict-free B frags

// Packed hidden-state storage:
// slab(par, col) = [g=16 rowgroups][kk=32 k-chunks][j=4][lane=32] u32 (each u32 = half2 pair)
// 2 * 16 * 65536 u32 = 8 MB
__device__ unsigned int g_statesP[2 * 16 * 16 * 32 * 4 * 32];
// logit partials, triple buffered: [3][NT][B][2]
__device__ float g_zpart[3 * NT * B_ * 2];
// per-CTA completed-step counters
__device__ int g_flags[NCTA];

__device__ __forceinline__ int ld_acquire(const int* p) {
    int v;
    asm volatile("ld.global.acquire.gpu.b32 %0, [%1];" : "=r"(v) : "l"(p) : "memory");
    return v;
}
__device__ __forceinline__ void st_release(int* p, int v) {
    asm volatile("st.global.release.gpu.b32 [%0], %1;" :: "l"(p), "r"(v) : "memory");
}
__device__ __forceinline__ unsigned ldg_cg_u32(const unsigned* p) {
    unsigned v;
    asm volatile("ld.global.cg.b32 %0, [%1];" : "=r"(v) : "l"(p));
    return v;
}
__device__ __forceinline__ float ldg_cg_f32(const float* p) {
    float v;
    asm volatile("ld.global.cg.f32 %0, [%1];" : "=f"(v) : "l"(p));
    return v;
}

__device__ __forceinline__ void mma16816(float acc[4],
    unsigned a0, unsigned a1, unsigned a2, unsigned a3,
    unsigned b0, unsigned b1)
{
    asm volatile(
        "mma.sync.aligned.m16n8k16.row.col.f32.f16.f16.f32 "
        "{%0,%1,%2,%3}, {%4,%5,%6,%7}, {%8,%9}, {%0,%1,%2,%3};"
        : "+f"(acc[0]), "+f"(acc[1]), "+f"(acc[2]), "+f"(acc[3])
        : "r"(a0), "r"(a1), "r"(a2), "r"(a3), "r"(b0), "r"(b1));
}

__device__ __forceinline__ unsigned* pslab(int par, int col) {
    return g_statesP + (((par << 4) + col) << 16);   // 65536 u32 per slab
}

// K=512 half-GEMM: A from packed slab, B from SMEM weight slice at kofs
__device__ __forceinline__ void gemm_half(
    const unsigned* __restrict__ Aslab, const __half* __restrict__ Wt, int kofs,
    int g, int lane, int q, int tg, float acc[4][4])
{
    const unsigned* A = Aslab + (g << 12) + lane;
#pragma unroll 4
    for (int kk = 0; kk < 32; ++kk) {
        unsigned a0 = ldg_cg_u32(A + (kk << 7));
        unsigned a1 = ldg_cg_u32(A + (kk << 7) + 32);
        unsigned a2 = ldg_cg_u32(A + (kk << 7) + 64);
        unsigned a3 = ldg_cg_u32(A + (kk << 7) + 96);
#pragma unroll
        for (int f = 0; f < 4; ++f) {
            const __half* bp = Wt + (8 * f + q) * WT_STRIDE + kofs + (kk << 4) + (tg << 1);
            unsigned b0 = *reinterpret_cast<const unsigned*>(bp);
            unsigned b1 = *reinterpret_cast<const unsigned*>(bp + 8);
            mma16816(acc[f], a0, a1, a2, a3, b0, b1);
        }
    }
}

__device__ __forceinline__ float elu1(float v) {
    return v > 0.f ? v : expm1f(v);
}

__device__ __forceinline__ unsigned packh2(float a, float b) {
    __half2 h = __floats2half2_rn(a, b);
    return *reinterpret_cast<unsigned*>(&h);
}

// log p(x) for one finished step, one batch element
__device__ __forceinline__ float reduce_logp(int tstep, int b,
    const int* __restrict__ x, const float* __restrict__ bout)
{
    int s = tstep - 1;
    int r = s >> 4, p = s & 15;
    int c = (r & 1) ? (15 - p) : p;
    float z0 = bout[0], z1 = bout[1];
    const float* zp = g_zpart + (tstep % 3) * (NT * B_ * 2) + b * 2;
#pragma unroll
    for (int nn = 0; nn < NT; ++nn) {
        z0 += ldg_cg_f32(zp + nn * (B_ * 2));
        z1 += ldg_cg_f32(zp + nn * (B_ * 2) + 1);
    }
    int spin = x[b * 256 + r * 16 + c];
    float mz = fmaxf(z0, z1);
    float lse = mz + logf(expf(z0 - mz) + expf(z1 - mz));
    return (spin ? z1 : z0) - lse;
}

__global__ void rnn2d_init_kernel() {
    if (threadIdx.x < NCTA) g_flags[threadIdx.x] = 0;
}

__global__ void __launch_bounds__(128) rnn2d_main_kernel(
    const int* __restrict__ x,
    const float* __restrict__ Wih, const float* __restrict__ Wiv,
    const float* __restrict__ Wch, const float* __restrict__ bch,
    const float* __restrict__ Wcv, const float* __restrict__ Wout,
    const float* __restrict__ bout, float* __restrict__ out)
{
    extern __shared__ unsigned char smem[];
    __half* Wt  = (__half*)smem;                                 // [32][WT_STRIDE]
    float* sWih = (float*)(smem + N_TILE * WT_STRIDE * 2);       // [2][32]
    float* sWiv = sWih + 64;                                     // [2][32]
    float* sBch = sWiv + 64;                                     // [32]
    float* sWo0 = sBch + 32;                                     // [32]
    float* sWo1 = sWo0 + 32;                                     // [32]

    const int bx   = blockIdx.x;
    const int n    = bx >> 2, m = bx & 3;
    const int tid  = threadIdx.x, wid = tid >> 5, lane = tid & 31;
    const int n0   = n * N_TILE;
    const int q    = lane >> 2, tg = lane & 3;
    const int g    = m * 4 + wid;           // row group (16 rows each)
    const int rowA = (g << 4) + q;          // batch row for c0/c1 (c2/c3 = +8)

    // ---- load resident weight slice: Wt[j][k] = W[k][n0+j], k<512 -> Wch, else Wcv
    for (int i = tid; i < N_TILE * 1024; i += 128) {
        int j = i >> 10, k = i & 1023;
        float w = (k < U_) ? Wch[k * U_ + n0 + j] : Wcv[(k - U_) * U_ + n0 + j];
        Wt[j * WT_STRIDE + k] = __float2half_rn(w);
    }
    if (tid < 32) {
        sWih[tid]      = Wih[n0 + tid];
        sWih[32 + tid] = Wih[U_ + n0 + tid];
        sWiv[tid]      = Wiv[n0 + tid];
        sWiv[32 + tid] = Wiv[U_ + n0 + tid];
        sBch[tid]      = bch[n0 + tid];
        sWo0[tid]      = Wout[(n0 + tid) * 2 + 0];
        sWo1[tid]      = Wout[(n0 + tid) * 2 + 1];
    }
    __syncthreads();

    float lp = 0.f;
    const int bred = (m << 6) + tid;   // reducer batch index (n==0 CTAs, tid<64)

#pragma unroll 1
    for (int t = 1; t <= T_STEPS; ++t) {
        const int s = t - 1;
        const int r = s >> 4, p = s & 15;
        const int c  = (r & 1) ? (15 - p) : p;
        const int cp = (r & 1) ? (c + 1) : (c - 1);   // previously-scanned column

        if (t > 1) {
            if (tid < NCTA) {
                while (ld_acquire(&g_flags[tid]) < t - 1) { }
            }
            __syncthreads();
        }

        float acc[4][4];
#pragma unroll
        for (int f = 0; f < 4; ++f) acc[f][0] = acc[f][1] = acc[f][2] = acc[f][3] = 0.f;

        if (p > 0) gemm_half(pslab(r & 1, cp),       Wt, 0,   g, lane, q, tg, acc);  // h part
        if (r > 0) gemm_half(pslab((r - 1) & 1, c),  Wt, 512, g, lane, q, tg, acc);  // cv part

        // ---- epilogue: bias select, elu, logit partials, packed fp16 store
        const int bA = rowA, bB = rowA + 8;
        int sLa = 0, sLb = 0, sUa = 0, sUb = 0;
        if (p > 0) { sLa = x[bA * 256 + r * 16 + cp];       sLb = x[bB * 256 + r * 16 + cp]; }
        if (r > 0) { sUa = x[bA * 256 + (r - 1) * 16 + c];  sUb = x[bB * 256 + (r - 1) * 16 + c]; }

        float z0a = 0.f, z1a = 0.f, z0b = 0.f, z1b = 0.f;
        unsigned* Pout = pslab(r & 1, c) + (g << 12) + lane;
#pragma unroll
        for (int f = 0; f < 4; ++f) {
            int u0 = 8 * f + tg * 2;
            float v0 = acc[f][0] + sBch[u0];
            float v1 = acc[f][1] + sBch[u0 + 1];
            float v2 = acc[f][2] + sBch[u0];
            float v3 = acc[f][3] + sBch[u0 + 1];
            if (p > 0) {
                v0 += sWih[sLa * 32 + u0]; v1 += sWih[sLa * 32 + u0 + 1];
                v2 += sWih[sLb * 32 + u0]; v3 += sWih[sLb * 32 + u0 + 1];
            }
            if (r > 0) {
                v0 += sWiv[sUa * 32 + u0]; v1 += sWiv[sUa * 32 + u0 + 1];
                v2 += sWiv[sUb * 32 + u0]; v3 += sWiv[sUb * 32 + u0 + 1];
            }
            v0 = elu1(v0); v1 = elu1(v1); v2 = elu1(v2); v3 = elu1(v3);

            z0a += v0 * sWo0[u0] + v1 * sWo0[u0 + 1];
            z1a += v0 * sWo1[u0] + v1 * sWo1[u0 + 1];
            z0b += v2 * sWo0[u0] + v3 * sWo0[u0 + 1];
            z1b += v2 * sWo1[u0] + v3 * sWo1[u0 + 1];

            int kk = (n0 + 8 * f) >> 4;
            int j0 = (f & 1) * 2;
            Pout[(kk << 7) + (j0 << 5)]       = packh2(v0, v1);
            Pout[(kk << 7) + ((j0 + 1) << 5)] = packh2(v2, v3);
        }
        // quad-reduce logit partials (lanes of a quad share rows, cover 8 cols each)
        z0a += __shfl_xor_sync(0xffffffffu, z0a, 1);
        z0a += __shfl_xor_sync(0xffffffffu, z0a, 2);
        z1a += __shfl_xor_sync(0xffffffffu, z1a, 1);
        z1a += __shfl_xor_sync(0xffffffffu, z1a, 2);
        z0b += __shfl_xor_sync(0xffffffffu, z0b, 1);
        z0b += __shfl_xor_sync(0xffffffffu, z0b, 2);
        z1b += __shfl_xor_sync(0xffffffffu, z1b, 1);
        z1b += __shfl_xor_sync(0xffffffffu, z1b, 2);
        if (tg == 0) {
            float* zp = g_zpart + ((t % 3) * NT + n) * (B_ * 2);
            zp[bA * 2 + 0] = z0a;  zp[bA * 2 + 1] = z1a;
            zp[bB * 2 + 0] = z0b;  zp[bB * 2 + 1] = z1b;
        }

        __syncthreads();
        if (tid == 0) st_release(&g_flags[bx], t);

        // off-critical-path: finish log-softmax for previous step
        if (n == 0 && t >= 2 && tid < 64) {
            lp += reduce_logp(t - 1, bred, x, bout);
        }
    }

    // final step's reduction + output
    if (tid < NCTA) {
        while (ld_acquire(&g_flags[tid]) < T_STEPS) { }
    }
    __syncthreads();
    if (n == 0 && tid < 64) {
        lp += reduce_logp(T_STEPS, bred, x, bout);
        out[bred] = lp;
    }
}

extern "C" void kernel_launch(void* const* d_in, const int* in_sizes, int n_in,
                              void* d_out, int out_size)
{
    (void)in_sizes; (void)n_in; (void)out_size;
    const int*   x    = (const int*)  d_in[0];
    const float* Wih  = (const float*)d_in[1];
    const float* Wiv  = (const float*)d_in[2];
    const float* Wch  = (const float*)d_in[3];
    const float* bch  = (const float*)d_in[4];
    const float* Wcv  = (const float*)d_in[5];
    const float* Wout = (const float*)d_in[6];
    const float* bout = (const float*)d_in[7];
    float* out = (float*)d_out;

    const int smem_bytes = N_TILE * WT_STRIDE * 2 + (64 + 64 + 32 + 32 + 32) * 4;
    cudaFuncSetAttribute(rnn2d_main_kernel,
                         cudaFuncAttributeMaxDynamicSharedMemorySize, smem_bytes);

    rnn2d_init_kernel<<<1, 64>>>();
    rnn2d_main_kernel<<<NCTA, 128, smem_bytes>>>(
        x, Wih, Wiv, Wch, bch, Wcv, Wout, bout, out);
}

// round 3
// speedup vs baseline: 1.1514x; 1.1514x over previous
#include <cuda_runtime.h>
#include <cuda_fp16.h>
#include <math.h>

// Problem constants
#define B_      256
#define L_      16
#define U_      512
#define T_STEPS 256
#define NT      16      // N tiles (512 / 32)
#define MG      8       // m-groups (256 / 32)
#define N_TILE  32
#define M_TILE  32
#define NCOMP   128     // compute CTAs
#define NRED    8       // reducer CTAs
#define WT_STRIDE 1032  // padded row stride (halfs), conflict-free B frags
#define ZDEPTH  8

// Packed hidden-state storage:
// slab(par, col) = [g=16 rowgroups][kk=32 k-chunks][j=4][lane=32] u32 (half2)
__device__ unsigned int g_statesP[2 * 16 * 16 * 32 * 4 * 32];
// logit partials: [ZDEPTH][NT][2 halves][B] float2
__device__ float2 g_zpart[ZDEPTH * NT * 2 * B_];
// per-CTA completed-step counters (grouped by m), reducer flags
__device__ int g_flags[NCOMP];
__device__ int g_rflags[NRED];

__device__ __forceinline__ int ld_acquire(const int* p) {
    int v;
    asm volatile("ld.global.acquire.gpu.b32 %0, [%1];" : "=r"(v) : "l"(p) : "memory");
    return v;
}
__device__ __forceinline__ void st_release(int* p, int v) {
    asm volatile("st.global.release.gpu.b32 [%0], %1;" :: "l"(p), "r"(v) : "memory");
}
__device__ __forceinline__ unsigned ldg_cg_u32(const unsigned* p) {
    unsigned v;
    asm volatile("ld.global.cg.b32 %0, [%1];" : "=r"(v) : "l"(p));
    return v;
}
__device__ __forceinline__ float2 ldg_cg_f2(const float2* p) {
    float2 v;
    asm volatile("ld.global.cg.v2.f32 {%0,%1}, [%2];" : "=f"(v.x), "=f"(v.y) : "l"(p));
    return v;
}

__device__ __forceinline__ void mma16816(float acc[4],
    unsigned a0, unsigned a1, unsigned a2, unsigned a3,
    unsigned b0, unsigned b1)
{
    asm volatile(
        "mma.sync.aligned.m16n8k16.row.col.f32.f16.f16.f32 "
        "{%0,%1,%2,%3}, {%4,%5,%6,%7}, {%8,%9}, {%0,%1,%2,%3};"
        : "+f"(acc[0]), "+f"(acc[1]), "+f"(acc[2]), "+f"(acc[3])
        : "r"(a0), "r"(a1), "r"(a2), "r"(a3), "r"(b0), "r"(b1));
}

__device__ __forceinline__ unsigned* pslab(int par, int col) {
    return g_statesP + (((par << 4) + col) << 16);   // 65536 u32 per slab
}

// K=512 half-GEMM: A from packed slab (rowgroup g), B from SMEM weights at kofs.
// Warp computes 16 rows x 16 cols; jrow = 16*h + q selects the col block.
__device__ __forceinline__ void gemm_half(
    const unsigned* __restrict__ Aslab, const __half* __restrict__ Wt, int kofs,
    int g, int lane, int jrow, int tg, float acc[2][4])
{
    const unsigned* A = Aslab + (g << 12) + lane;
    const __half* W0 = Wt + jrow * WT_STRIDE + kofs + (tg << 1);
#pragma unroll 4
    for (int kk = 0; kk < 32; ++kk) {
        unsigned a0 = ldg_cg_u32(A + (kk << 7));
        unsigned a1 = ldg_cg_u32(A + (kk << 7) + 32);
        unsigned a2 = ldg_cg_u32(A + (kk << 7) + 64);
        unsigned a3 = ldg_cg_u32(A + (kk << 7) + 96);
#pragma unroll
        for (int f = 0; f < 2; ++f) {
            const __half* bp = W0 + f * 8 * WT_STRIDE + (kk << 4);
            unsigned b0 = *reinterpret_cast<const unsigned*>(bp);
            unsigned b1 = *reinterpret_cast<const unsigned*>(bp + 8);
            mma16816(acc[f], a0, a1, a2, a3, b0, b1);
        }
    }
}

__device__ __forceinline__ float elu1(float v) {
    return v > 0.f ? v : (__expf(v) - 1.f);
}
__device__ __forceinline__ unsigned packh2(float a, float b) {
    __half2 h = __floats2half2_rn(a, b);
    return *reinterpret_cast<unsigned*>(&h);
}

__global__ void rnn2d_init_kernel() {
    if (threadIdx.x < NCOMP) g_flags[threadIdx.x] = 0;
    if (threadIdx.x < NRED)  g_rflags[threadIdx.x] = 0;
}

__global__ void __launch_bounds__(128) rnn2d_main_kernel(
    const int* __restrict__ x,
    const float* __restrict__ Wih, const float* __restrict__ Wiv,
    const float* __restrict__ Wch, const float* __restrict__ bch,
    const float* __restrict__ Wcv, const float* __restrict__ Wout,
    const float* __restrict__ bout, float* __restrict__ out)
{
    extern __shared__ unsigned char smem[];
    __half* Wt  = (__half*)smem;                                 // [32][WT_STRIDE]
    float* sWih = (float*)(smem + N_TILE * WT_STRIDE * 2);       // [2][32]
    float* sWiv = sWih + 64;                                     // [2][32]
    float* sBch = sWiv + 64;                                     // [32]
    float* sWo0 = sBch + 32;                                     // [32]
    float* sWo1 = sWo0 + 32;                                     // [32]
    unsigned char* sx = (unsigned char*)(sWo1 + 32);             // [256 cells][32 rows]

    const int bx  = blockIdx.x;
    const int tid = threadIdx.x;

    if (bx >= NCOMP) {
        // ---------------- reducer CTA (off the critical path) ----------------
        const int m = bx - NCOMP;
        for (int i = tid; i < 8192; i += 128) {
            int rl = i >> 8, cell = i & 255;
            sx[cell * 32 + rl] = (unsigned char)x[(32 * m + rl) * 256 + cell];
        }
        __syncthreads();
        if (tid >= 32) return;

        const int lane = tid;
        const int b = 32 * m + lane;
        const float bo0 = bout[0], bo1 = bout[1];
        int* myflags = g_flags + m * 16;
        float lp = 0.f;
        for (int t = 1; t <= T_STEPS; ++t) {
            if (lane < 16) {
                while (ld_acquire(myflags + lane) < t) { }
            }
            __syncwarp();
            asm volatile("membar.gl;" ::: "memory");
            float z0 = bo0, z1 = bo1;
            const float2* zp = g_zpart + ((t & (ZDEPTH - 1)) * NT) * (2 * B_) + b;
#pragma unroll
            for (int nn = 0; nn < NT; ++nn) {
#pragma unroll
                for (int hh = 0; hh < 2; ++hh) {
                    float2 v = ldg_cg_f2(zp + nn * (2 * B_) + hh * B_);
                    z0 += v.x; z1 += v.y;
                }
            }
            int s = t - 1, r = s >> 4, p = s & 15;
            int c = (r & 1) ? (15 - p) : p;
            int spin = sx[(r * 16 + c) * 32 + lane];
            float mz = fmaxf(z0, z1);
            float lse = mz + logf(expf(z0 - mz) + expf(z1 - mz));
            lp += (spin ? z1 : z0) - lse;
            __syncwarp();
            if (lane == 0) st_release(&g_rflags[m], t);
        }
        out[b] = lp;
        return;
    }

    // ---------------- compute CTA ----------------
    const int m = bx >> 4, n = bx & 15;
    const int wid = tid >> 5, lane = tid & 31;
    const int n0 = n * N_TILE;
    const int q = lane >> 2, tg = lane & 3;
    const int h  = wid >> 1;          // n-half within the 32-col tile
    const int gl = wid & 1;           // row half within the 32-row tile
    const int g  = 2 * m + gl;        // global 16-row group
    const int jrow = 16 * h + q;      // Wt row base

    for (int i = tid; i < N_TILE * 1024; i += 128) {
        int j = i >> 10, k = i & 1023;
        float w = (k < U_) ? Wch[k * U_ + n0 + j] : Wcv[(k - U_) * U_ + n0 + j];
        Wt[j * WT_STRIDE + k] = __float2half_rn(w);
    }
    if (tid < 32) {
        sWih[tid]      = Wih[n0 + tid];
        sWih[32 + tid] = Wih[U_ + n0 + tid];
        sWiv[tid]      = Wiv[n0 + tid];
        sWiv[32 + tid] = Wiv[U_ + n0 + tid];
        sBch[tid]      = bch[n0 + tid];
        sWo0[tid]      = Wout[(n0 + tid) * 2 + 0];
        sWo1[tid]      = Wout[(n0 + tid) * 2 + 1];
    }
    for (int i = tid; i < 8192; i += 128) {
        int rl = i >> 8, cell = i & 255;
        sx[cell * 32 + rl] = (unsigned char)x[(32 * m + rl) * 256 + cell];
    }
    __syncthreads();

    int* myflags = g_flags + m * 16;
    const int rlA = 16 * gl + q;           // local batch row (c0,c1); +8 for c2,c3

#pragma unroll 1
    for (int t = 1; t <= T_STEPS; ++t) {
        const int s = t - 1;
        const int r = s >> 4, p = s & 15;
        const int c  = (r & 1) ? (15 - p) : p;
        const int cp = (r & 1) ? (c + 1) : (c - 1);
        const bool has_h = (p > 0), has_v = (r > 0);

        float acc[2][4];
#pragma unroll
        for (int f = 0; f < 2; ++f)
            acc[f][0] = acc[f][1] = acc[f][2] = acc[f][3] = 0.f;

        // cv half: dep step = t - (2p+1) <= t-3 when p>=1 -> already visible,
        // compute BEFORE waiting to hide sync latency.
        if (has_v && has_h)
            gemm_half(pslab((r - 1) & 1, c), Wt, 512, g, lane, jrow, tg, acc);

        if (t > 1) {
            if (tid < 16) {
                while (ld_acquire(myflags + tid) < t - 1) { }
            }
            if (tid == 16) {   // z-buffer back-pressure (almost never blocks)
                while (ld_acquire(&g_rflags[m]) < t - ZDEPTH) { }
            }
            __syncthreads();
        }

        if (has_v && !has_h)   // p==0: cv dep IS t-1, must run post-wait
            gemm_half(pslab((r - 1) & 1, c), Wt, 512, g, lane, jrow, tg, acc);
        if (has_h)
            gemm_half(pslab(r & 1, cp), Wt, 0, g, lane, jrow, tg, acc);

        // ---- epilogue
        int sLa = 0, sLb = 0, sUa = 0, sUb = 0;
        if (has_h) {
            sLa = sx[(r * 16 + cp) * 32 + rlA];
            sLb = sx[(r * 16 + cp) * 32 + rlA + 8];
        }
        if (has_v) {
            sUa = sx[((r - 1) * 16 + c) * 32 + rlA];
            sUb = sx[((r - 1) * 16 + c) * 32 + rlA + 8];
        }

        float z0a = 0.f, z1a = 0.f, z0b = 0.f, z1b = 0.f;
        unsigned* Pout = pslab(r & 1, c) + ((g * 32 + (n0 >> 4) + h) << 7) + lane;
#pragma unroll
        for (int f = 0; f < 2; ++f) {
            int u0 = 16 * h + 8 * f + 2 * tg;
            float v0 = acc[f][0] + sBch[u0];
            float v1 = acc[f][1] + sBch[u0 + 1];
            float v2 = acc[f][2] + sBch[u0];
            float v3 = acc[f][3] + sBch[u0 + 1];
            if (has_h) {
                v0 += sWih[sLa * 32 + u0]; v1 += sWih[sLa * 32 + u0 + 1];
                v2 += sWih[sLb * 32 + u0]; v3 += sWih[sLb * 32 + u0 + 1];
            }
            if (has_v) {
                v0 += sWiv[sUa * 32 + u0]; v1 += sWiv[sUa * 32 + u0 + 1];
                v2 += sWiv[sUb * 32 + u0]; v3 += sWiv[sUb * 32 + u0 + 1];
            }
            v0 = elu1(v0); v1 = elu1(v1); v2 = elu1(v2); v3 = elu1(v3);

            z0a += v0 * sWo0[u0] + v1 * sWo0[u0 + 1];
            z1a += v0 * sWo1[u0] + v1 * sWo1[u0 + 1];
            z0b += v2 * sWo0[u0] + v3 * sWo0[u0 + 1];
            z1b += v2 * sWo1[u0] + v3 * sWo1[u0 + 1];

            Pout[(2 * f) * 32]     = packh2(v0, v1);
            Pout[(2 * f + 1) * 32] = packh2(v2, v3);
        }
        // quad reduce: lanes of a quad (tg=0..3) share rows, cover the 16 cols
        z0a += __shfl_xor_sync(0xffffffffu, z0a, 1);
        z0a += __shfl_xor_sync(0xffffffffu, z0a, 2);
        z1a += __shfl_xor_sync(0xffffffffu, z1a, 1);
        z1a += __shfl_xor_sync(0xffffffffu, z1a, 2);
        z0b += __shfl_xor_sync(0xffffffffu, z0b, 1);
        z0b += __shfl_xor_sync(0xffffffffu, z0b, 2);
        z1b += __shfl_xor_sync(0xffffffffu, z1b, 1);
        z1b += __shfl_xor_sync(0xffffffffu, z1b, 2);
        if (tg == 0) {
            float2* zp = g_zpart + (((t & (ZDEPTH - 1)) * NT + n) * 2 + h) * B_;
            int bA = 32 * m + rlA;
            zp[bA]     = make_float2(z0a, z1a);
            zp[bA + 8] = make_float2(z0b, z1b);
        }

        __syncthreads();
        if (tid == 0) st_release(&g_flags[bx], t);
    }
}

extern "C" void kernel_launch(void* const* d_in, const int* in_sizes, int n_in,
                              void* d_out, int out_size)
{
    (void)in_sizes; (void)n_in; (void)out_size;
    const int*   x    = (const int*)  d_in[0];
    const float* Wih  = (const float*)d_in[1];
    const float* Wiv  = (const float*)d_in[2];
    const float* Wch  = (const float*)d_in[3];
    const float* bch  = (const float*)d_in[4];
    const float* Wcv  = (const float*)d_in[5];
    const float* Wout = (const float*)d_in[6];
    const float* bout = (const float*)d_in[7];
    float* out = (float*)d_out;

    const int smem_bytes = N_TILE * WT_STRIDE * 2 + (64 + 64 + 32 + 32 + 32) * 4 + 8192;
    cudaFuncSetAttribute(rnn2d_main_kernel,
                         cudaFuncAttributeMaxDynamicSharedMemorySize, smem_bytes);

    rnn2d_init_kernel<<<1, 128>>>();
    rnn2d_main_kernel<<<NCOMP + NRED, 128, smem_bytes>>>(
        x, Wih, Wiv, Wch, bch, Wcv, Wout, bout, out);
}

// round 4
// speedup vs baseline: 3.1042x; 2.6961x over previous
#include <cuda_runtime.h>
#include <cuda_fp16.h>
#include <math.h>

// Problem constants
#define B_      256
#define L_      16
#define U_      512
#define T_STEPS 256
#define NT      16      // N tiles (512 / 32)
#define N_TILE  32
#define NCOMP   128     // compute CTAs
#define NRED    8       // reducer CTAs
#define WT_STRIDE 1032  // padded row stride (halfs), conflict-free B frags
#define ZDEPTH  8

// Packed hidden-state storage:
// slab(par, col) = [g=16 rowgroups][kk=32 k-chunks][j=4][lane=32] u32 (half2)
__device__ unsigned int g_statesP[2 * 16 * 16 * 32 * 4 * 32];
// logit partials: [ZDEPTH][NT][2 halves][B] float2
__device__ float2 g_zpart[ZDEPTH * NT * 2 * B_];
// per-CTA completed-step counters (grouped by m), reducer flags
__device__ int g_flags[NCOMP];
__device__ int g_rflags[NRED];

// ---- smem layout offsets (bytes) ----
#define SM_WT    0
#define SM_SA    66048                  // 32*1032*2, 16B aligned
#define SM_SMALL (SM_SA + 65536)        // two 32KB A-staging buffers
#define SM_SX    (SM_SMALL + 896)
#define SM_TOTAL (SM_SX + 8192)

__device__ __forceinline__ int ld_acquire(const int* p) {
    int v;
    asm volatile("ld.global.acquire.gpu.b32 %0, [%1];" : "=r"(v) : "l"(p) : "memory");
    return v;
}
__device__ __forceinline__ void st_release(int* p, int v) {
    asm volatile("st.global.release.gpu.b32 [%0], %1;" :: "l"(p), "r"(v) : "memory");
}
__device__ __forceinline__ float2 ldg_cg_f2(const float2* p) {
    float2 v;
    asm volatile("ld.global.cg.v2.f32 {%0,%1}, [%2];" : "=f"(v.x), "=f"(v.y) : "l"(p));
    return v;
}
__device__ __forceinline__ void cp_async16(unsigned smem_addr, const void* gptr) {
    asm volatile("cp.async.cg.shared.global [%0], [%1], 16;"
                 :: "r"(smem_addr), "l"(gptr));
}
__device__ __forceinline__ void cp_commit() {
    asm volatile("cp.async.commit_group;");
}
template <int N>
__device__ __forceinline__ void cp_wait() {
    asm volatile("cp.async.wait_group %0;" :: "n"(N) : "memory");
}

__device__ __forceinline__ void mma16816(float acc[4],
    unsigned a0, unsigned a1, unsigned a2, unsigned a3,
    unsigned b0, unsigned b1)
{
    asm volatile(
        "mma.sync.aligned.m16n8k16.row.col.f32.f16.f16.f32 "
        "{%0,%1,%2,%3}, {%4,%5,%6,%7}, {%8,%9}, {%0,%1,%2,%3};"
        : "+f"(acc[0]), "+f"(acc[1]), "+f"(acc[2]), "+f"(acc[3])
        : "r"(a0), "r"(a1), "r"(a2), "r"(a3), "r"(b0), "r"(b1));
}

__device__ __forceinline__ unsigned* pslab(int par, int col) {
    return g_statesP + (((par << 4) + col) << 16);   // 65536 u32 per slab
}

// stage 32KB (CTA's two 16-row groups, contiguous) global -> smem, async
__device__ __forceinline__ void stage_copy(unsigned dst_base, const unsigned* src, int tid) {
#pragma unroll
    for (int i = 0; i < 16; ++i)
        cp_async16(dst_base + tid * 16 + i * 2048, src + tid * 4 + i * 512);
    cp_commit();
}

// K=512 half-GEMM from SMEM-staged A; B from resident SMEM weights at kofs.
__device__ __forceinline__ void gemm_smem(
    const unsigned* __restrict__ sA, const __half* __restrict__ Wt, int kofs,
    int gl, int lane, int jrow, int tg, float acc[2][4])
{
    const unsigned* A = sA + (gl << 12) + lane;
    const __half* W0 = Wt + jrow * WT_STRIDE + kofs + (tg << 1);
#pragma unroll 8
    for (int kk = 0; kk < 32; ++kk) {
        unsigned a0 = A[(kk << 7)];
        unsigned a1 = A[(kk << 7) + 32];
        unsigned a2 = A[(kk << 7) + 64];
        unsigned a3 = A[(kk << 7) + 96];
#pragma unroll
        for (int f = 0; f < 2; ++f) {
            const __half* bp = W0 + f * 8 * WT_STRIDE + (kk << 4);
            unsigned b0 = *reinterpret_cast<const unsigned*>(bp);
            unsigned b1 = *reinterpret_cast<const unsigned*>(bp + 8);
            mma16816(acc[f], a0, a1, a2, a3, b0, b1);
        }
    }
}

__device__ __forceinline__ float elu1(float v) {
    return v > 0.f ? v : (__expf(v) - 1.f);
}
__device__ __forceinline__ unsigned packh2(float a, float b) {
    __half2 h = __floats2half2_rn(a, b);
    return *reinterpret_cast<unsigned*>(&h);
}

__global__ void rnn2d_init_kernel() {
    if (threadIdx.x < NCOMP) g_flags[threadIdx.x] = 0;
    if (threadIdx.x < NRED)  g_rflags[threadIdx.x] = 0;
}

__global__ void __launch_bounds__(128) rnn2d_main_kernel(
    const int* __restrict__ x,
    const float* __restrict__ Wih, const float* __restrict__ Wiv,
    const float* __restrict__ Wch, const float* __restrict__ bch,
    const float* __restrict__ Wcv, const float* __restrict__ Wout,
    const float* __restrict__ bout, float* __restrict__ out)
{
    extern __shared__ unsigned char smem[];
    __half*   Wt   = (__half*)(smem + SM_WT);            // [32][WT_STRIDE]
    unsigned* sA   = (unsigned*)(smem + SM_SA);          // [2][8192] u32
    float* sWih = (float*)(smem + SM_SMALL);             // [2][32]
    float* sWiv = sWih + 64;                             // [2][32]
    float* sBch = sWiv + 64;                             // [32]
    float* sWo0 = sBch + 32;                             // [32]
    float* sWo1 = sWo0 + 32;                             // [32]
    unsigned char* sx = (unsigned char*)(smem + SM_SX);  // [256 cells][32 rows]

    const int bx  = blockIdx.x;
    const int tid = threadIdx.x;

    if (bx >= NCOMP) {
        // ---------------- reducer CTA (off the critical path) ----------------
        const int m = bx - NCOMP;
        for (int i = tid; i < 8192; i += 128) {
            int rl = i >> 8, cell = i & 255;
            sx[cell * 32 + rl] = (unsigned char)x[(32 * m + rl) * 256 + cell];
        }
        __syncthreads();
        if (tid >= 32) return;

        const int lane = tid;
        const int b = 32 * m + lane;
        const float bo0 = bout[0], bo1 = bout[1];
        int* myflags = g_flags + m * 16;
        float lp = 0.f;
        for (int t = 1; t <= T_STEPS; ++t) {
            if (lane < 16) {
                while (ld_acquire(myflags + lane) < t) { }
            }
            __syncwarp();
            asm volatile("membar.gl;" ::: "memory");
            float z0 = bo0, z1 = bo1;
            const float2* zp = g_zpart + ((t & (ZDEPTH - 1)) * NT) * (2 * B_) + b;
#pragma unroll
            for (int nn = 0; nn < NT; ++nn) {
#pragma unroll
                for (int hh = 0; hh < 2; ++hh) {
                    float2 v = ldg_cg_f2(zp + nn * (2 * B_) + hh * B_);
                    z0 += v.x; z1 += v.y;
                }
            }
            int s = t - 1, r = s >> 4, p = s & 15;
            int c = (r & 1) ? (15 - p) : p;
            int spin = sx[(r * 16 + c) * 32 + lane];
            float mz = fmaxf(z0, z1);
            float lse = mz + logf(expf(z0 - mz) + expf(z1 - mz));
            lp += (spin ? z1 : z0) - lse;
            __syncwarp();
            if (lane == 0) st_release(&g_rflags[m], t);
        }
        out[b] = lp;
        return;
    }

    // ---------------- compute CTA ----------------
    const int m = bx >> 4, n = bx & 15;
    const int wid = tid >> 5, lane = tid & 31;
    const int n0 = n * N_TILE;
    const int q = lane >> 2, tg = lane & 3;
    const int h  = wid >> 1;          // n-half within the 32-col tile
    const int gl = wid & 1;           // row half within the 32-row tile
    const int g  = 2 * m + gl;        // global 16-row group
    const int jrow = 16 * h + q;      // Wt row base
    const unsigned sA_base = (unsigned)__cvta_generic_to_shared(sA);

    for (int i = tid; i < N_TILE * 1024; i += 128) {
        int j = i >> 10, k = i & 1023;
        float w = (k < U_) ? Wch[k * U_ + n0 + j] : Wcv[(k - U_) * U_ + n0 + j];
        Wt[j * WT_STRIDE + k] = __float2half_rn(w);
    }
    if (tid < 32) {
        sWih[tid]      = Wih[n0 + tid];
        sWih[32 + tid] = Wih[U_ + n0 + tid];
        sWiv[tid]      = Wiv[n0 + tid];
        sWiv[32 + tid] = Wiv[U_ + n0 + tid];
        sBch[tid]      = bch[n0 + tid];
        sWo0[tid]      = Wout[(n0 + tid) * 2 + 0];
        sWo1[tid]      = Wout[(n0 + tid) * 2 + 1];
    }
    for (int i = tid; i < 8192; i += 128) {
        int rl = i >> 8, cell = i & 255;
        sx[cell * 32 + rl] = (unsigned char)x[(32 * m + rl) * 256 + cell];
    }
    __syncthreads();

    int* myflags = g_flags + m * 16;
    const int rlA = 16 * gl + q;           // local batch row (c0,c1); +8 for c2,c3

#pragma unroll 1
    for (int t = 1; t <= T_STEPS; ++t) {
        const int s = t - 1;
        const int r = s >> 4, p = s & 15;
        const int c  = (r & 1) ? (15 - p) : p;
        const int cp = (r & 1) ? (c + 1) : (c - 1);
        const bool has_h = (p > 0), has_v = (r > 0);

        const unsigned* cvsrc = pslab((r - 1) & 1, c) + (m << 13);
        const unsigned* hsrc  = pslab(r & 1, cp)      + (m << 13);

        // cv tile dep = step t-(2p+1) <= t-3 when p>=1: prefetch BEFORE waiting
        if (has_v && has_h) stage_copy(sA_base, cvsrc, tid);

        if (t > 1) {
            if (tid < 16) {
                while (ld_acquire(myflags + tid) < t - 1) { }
            }
            if (tid == 16) {   // z-buffer back-pressure (almost never blocks)
                while (ld_acquire(&g_rflags[m]) < t - ZDEPTH) { }
            }
            __syncthreads();
        }

        // h tile is fresh (t-1): start its async copy immediately after the wait
        if (has_h) stage_copy(sA_base + 32768, hsrc, tid);
        if (has_v && !has_h) stage_copy(sA_base, cvsrc, tid);   // p==0: dep IS t-1

        float acc[2][4];
#pragma unroll
        for (int f = 0; f < 2; ++f)
            acc[f][0] = acc[f][1] = acc[f][2] = acc[f][3] = 0.f;

        if (has_v) {
            if (has_h) cp_wait<1>(); else cp_wait<0>();
            __syncthreads();
            gemm_smem(sA, Wt, 512, gl, lane, jrow, tg, acc);   // runs under h-copy latency
        }
        if (has_h) {
            cp_wait<0>();
            __syncthreads();
            gemm_smem(sA + 8192, Wt, 0, gl, lane, jrow, tg, acc);
        }

        // ---- epilogue
        int sLa = 0, sLb = 0, sUa = 0, sUb = 0;
        if (has_h) {
            sLa = sx[(r * 16 + cp) * 32 + rlA];
            sLb = sx[(r * 16 + cp) * 32 + rlA + 8];
        }
        if (has_v) {
            sUa = sx[((r - 1) * 16 + c) * 32 + rlA];
            sUb = sx[((r - 1) * 16 + c) * 32 + rlA + 8];
        }

        float z0a = 0.f, z1a = 0.f, z0b = 0.f, z1b = 0.f;
        unsigned* Pout = pslab(r & 1, c) + ((g * 32 + (n0 >> 4) + h) << 7) + lane;
#pragma unroll
        for (int f = 0; f < 2; ++f) {
            int u0 = 16 * h + 8 * f + 2 * tg;
            float v0 = acc[f][0] + sBch[u0];
            float v1 = acc[f][1] + sBch[u0 + 1];
            float v2 = acc[f][2] + sBch[u0];
            float v3 = acc[f][3] + sBch[u0 + 1];
            if (has_h) {
                v0 += sWih[sLa * 32 + u0]; v1 += sWih[sLa * 32 + u0 + 1];
                v2 += sWih[sLb * 32 + u0]; v3 += sWih[sLb * 32 + u0 + 1];
            }
            if (has_v) {
                v0 += sWiv[sUa * 32 + u0]; v1 += sWiv[sUa * 32 + u0 + 1];
                v2 += sWiv[sUb * 32 + u0]; v3 += sWiv[sUb * 32 + u0 + 1];
            }
            v0 = elu1(v0); v1 = elu1(v1); v2 = elu1(v2); v3 = elu1(v3);

            z0a += v0 * sWo0[u0] + v1 * sWo0[u0 + 1];
            z1a += v0 * sWo1[u0] + v1 * sWo1[u0 + 1];
            z0b += v2 * sWo0[u0] + v3 * sWo0[u0 + 1];
            z1b += v2 * sWo1[u0] + v3 * sWo1[u0 + 1];

            Pout[(2 * f) * 32]     = packh2(v0, v1);
            Pout[(2 * f + 1) * 32] = packh2(v2, v3);
        }
        // quad reduce: lanes of a quad (tg=0..3) share rows, cover the 16 cols
        z0a += __shfl_xor_sync(0xffffffffu, z0a, 1);
        z0a += __shfl_xor_sync(0xffffffffu, z0a, 2);
        z1a += __shfl_xor_sync(0xffffffffu, z1a, 1);
        z1a += __shfl_xor_sync(0xffffffffu, z1a, 2);
        z0b += __shfl_xor_sync(0xffffffffu, z0b, 1);
        z0b += __shfl_xor_sync(0xffffffffu, z0b, 2);
        z1b += __shfl_xor_sync(0xffffffffu, z1b, 1);
        z1b += __shfl_xor_sync(0xffffffffu, z1b, 2);
        if (tg == 0) {
            float2* zp = g_zpart + (((t & (ZDEPTH - 1)) * NT + n) * 2 + h) * B_;
            int bA = 32 * m + rlA;
            zp[bA]     = make_float2(z0a, z1a);
            zp[bA + 8] = make_float2(z0b, z1b);
        }

        __syncthreads();
        if (tid == 0) st_release(&g_flags[bx], t);
    }
}

extern "C" void kernel_launch(void* const* d_in, const int* in_sizes, int n_in,
                              void* d_out, int out_size)
{
    (void)in_sizes; (void)n_in; (void)out_size;
    const int*   x    = (const int*)  d_in[0];
    const float* Wih  = (const float*)d_in[1];
    const float* Wiv  = (const float*)d_in[2];
    const float* Wch  = (const float*)d_in[3];
    const float* bch  = (const float*)d_in[4];
    const float* Wcv  = (const float*)d_in[5];
    const float* Wout = (const float*)d_in[6];
    const float* bout = (const float*)d_in[7];
    float* out = (float*)d_out;

    cudaFuncSetAttribute(rnn2d_main_kernel,
                         cudaFuncAttributeMaxDynamicSharedMemorySize, SM_TOTAL);

    rnn2d_init_kernel<<<1, 128>>>();
    rnn2d_main_kernel<<<NCOMP + NRED, 128, SM_TOTAL>>>(
        x, Wih, Wiv, Wch, bch, Wcv, Wout, bout, out);
}

// round 5
// speedup vs baseline: 3.6864x; 1.1875x over previous
#include <cuda_runtime.h>
#include <cuda_fp16.h>
#include <math.h>

// Problem constants
#define B_      256
#define U_      512
#define T_STEPS 256
#define NTn     8       // n tiles (512 / 64)
#define N_TILE  64
#define NCOMP   128     // compute CTAs (16 m-groups x 8 n-tiles)
#define NRED    8       // reducer CTAs
#define WT_STRIDE 1032  // padded row stride (halfs): 2064B rows -> conflict-free LDSM
#define ZDEPTH  8

// Packed hidden-state storage:
// slab(par, col) = [m=16 rowgroups(16 rows)][kk=32][j=4][lane=32] u32 (half2)
__device__ unsigned int g_statesP[2 * 16 * 16 * 32 * 4 * 32];
// logit partials: [ZDEPTH][NTn][4 warps][B] float2
__device__ float2 g_zpart[ZDEPTH * NTn * 4 * B_];
// per-CTA completed-step counters (8 per m-group), reducer flags
__device__ int g_flags[NCOMP];
__device__ int g_rflags[NRED];

// ---- smem layout offsets (bytes) ----
#define SM_WT    0                       // 64 x 1032 halves = 132096 B
#define SM_SA    132096                  // two 16KB A-staging buffers
#define SM_SMALL (SM_SA + 32768)         // 448 floats = 1792 B
#define SM_SX    (SM_SMALL + 1792)
#define SM_TOTAL (SM_SX + 8192)          // 174848 B

__device__ __forceinline__ int ld_acquire(const int* p) {
    int v;
    asm volatile("ld.global.acquire.gpu.b32 %0, [%1];" : "=r"(v) : "l"(p) : "memory");
    return v;
}
__device__ __forceinline__ void st_release(int* p, int v) {
    asm volatile("st.global.release.gpu.b32 [%0], %1;" :: "l"(p), "r"(v) : "memory");
}
__device__ __forceinline__ float2 ldg_cg_f2(const float2* p) {
    float2 v;
    asm volatile("ld.global.cg.v2.f32 {%0,%1}, [%2];" : "=f"(v.x), "=f"(v.y) : "l"(p));
    return v;
}
__device__ __forceinline__ void cp_async16(unsigned smem_addr, const void* gptr) {
    asm volatile("cp.async.cg.shared.global [%0], [%1], 16;"
                 :: "r"(smem_addr), "l"(gptr));
}
__device__ __forceinline__ void cp_commit() {
    asm volatile("cp.async.commit_group;");
}
template <int N>
__device__ __forceinline__ void cp_wait() {
    asm volatile("cp.async.wait_group %0;" :: "n"(N) : "memory");
}

__device__ __forceinline__ void mma16816(float acc[4],
    unsigned a0, unsigned a1, unsigned a2, unsigned a3,
    unsigned b0, unsigned b1)
{
    asm volatile(
        "mma.sync.aligned.m16n8k16.row.col.f32.f16.f16.f32 "
        "{%0,%1,%2,%3}, {%4,%5,%6,%7}, {%8,%9}, {%0,%1,%2,%3};"
        : "+f"(acc[0]), "+f"(acc[1]), "+f"(acc[2]), "+f"(acc[3])
        : "r"(a0), "r"(a1), "r"(a2), "r"(a3), "r"(b0), "r"(b1));
}

__device__ __forceinline__ unsigned* pslab(int par, int col) {
    return g_statesP + (((par << 4) + col) << 16);   // 65536 u32 per slab
}

// stage 16KB (this CTA's 16-row group, contiguous) global -> smem, async
__device__ __forceinline__ void stage_copy16(unsigned dst_base, const unsigned* src, int tid) {
#pragma unroll
    for (int i = 0; i < 8; ++i)
        cp_async16(dst_base + tid * 16 + i * 2048, src + tid * 4 + i * 512);
    cp_commit();
}

// K=512 half-GEMM, A (16x512) + B (64-col weight slice) via ldmatrix.x4.
// aB: per-lane A address; bB: per-lane B address (kofs folded in by caller).
__device__ __forceinline__ void gemm_ldsm(unsigned aB, unsigned bB, float acc[2][4]) {
#pragma unroll 8
    for (int kk = 0; kk < 32; ++kk) {
        unsigned a0, a1, a2, a3, b0, b1, b2, b3;
        asm volatile("ldmatrix.sync.aligned.m8n8.x4.shared.b16 {%0,%1,%2,%3}, [%4];"
            : "=r"(a0), "=r"(a1), "=r"(a2), "=r"(a3) : "r"(aB));
        asm volatile("ldmatrix.sync.aligned.m8n8.x4.shared.b16 {%0,%1,%2,%3}, [%4];"
            : "=r"(b0), "=r"(b1), "=r"(b2), "=r"(b3) : "r"(bB));
        mma16816(acc[0], a0, a1, a2, a3, b0, b1);
        mma16816(acc[1], a0, a1, a2, a3, b2, b3);
        aB += 512;   // next k-chunk of A
        bB += 32;    // 16 halves forward in K
    }
}

__device__ __forceinline__ float elu1(float v) {
    return v > 0.f ? v : (__expf(v) - 1.f);
}
__device__ __forceinline__ unsigned packh2(float a, float b) {
    __half2 h = __floats2half2_rn(a, b);
    return *reinterpret_cast<unsigned*>(&h);
}

__global__ void rnn2d_init_kernel() {
    if (threadIdx.x < NCOMP) g_flags[threadIdx.x] = 0;
    if (threadIdx.x < NRED)  g_rflags[threadIdx.x] = 0;
}

__global__ void __launch_bounds__(128) rnn2d_main_kernel(
    const int* __restrict__ x,
    const float* __restrict__ Wih, const float* __restrict__ Wiv,
    const float* __restrict__ Wch, const float* __restrict__ bch,
    const float* __restrict__ Wcv, const float* __restrict__ Wout,
    const float* __restrict__ bout, float* __restrict__ out)
{
    extern __shared__ unsigned char smem[];
    __half*   Wt = (__half*)(smem + SM_WT);              // [64][WT_STRIDE]
    unsigned* sA = (unsigned*)(smem + SM_SA);            // [2][4096] u32
    float* sWih = (float*)(smem + SM_SMALL);             // [2][64]
    float* sWiv = sWih + 128;                            // [2][64]
    float* sBch = sWiv + 128;                            // [64]
    float* sWo0 = sBch + 64;                             // [64]
    float* sWo1 = sWo0 + 64;                             // [64]
    unsigned char* sx = (unsigned char*)(smem + SM_SX);

    const int bx  = blockIdx.x;
    const int tid = threadIdx.x;

    if (bx >= NCOMP) {
        // ---------------- reducer CTA (off the critical path) ----------------
        const int mr = bx - NCOMP;                 // handles rows 32*mr..32*mr+31
        for (int i = tid; i < 8192; i += 128) {
            int rl = i & 31, cell = i >> 5;
            sx[cell * 32 + rl] = (unsigned char)x[(32 * mr + rl) * 256 + cell];
        }
        __syncthreads();
        if (tid >= 32) return;

        const int lane = tid;
        const int b = 32 * mr + lane;
        const float bo0 = bout[0], bo1 = bout[1];
        int* myflags = g_flags + 16 * mr;          // 2 m-groups x 8 flags
        float lp = 0.f;
        for (int t = 1; t <= T_STEPS; ++t) {
            if (lane < 16) {
                while (ld_acquire(myflags + lane) < t) { }
            }
            __syncwarp();
            asm volatile("membar.gl;" ::: "memory");
            float z0 = bo0, z1 = bo1;
            const float2* zp = g_zpart + (t & (ZDEPTH - 1)) * (NTn * 4 * B_) + b;
#pragma unroll
            for (int i = 0; i < 32; ++i) {
                float2 v = ldg_cg_f2(zp + i * B_);
                z0 += v.x; z1 += v.y;
            }
            int s = t - 1, r = s >> 4, p = s & 15;
            int c = (r & 1) ? (15 - p) : p;
            int spin = sx[(r * 16 + c) * 32 + lane];
            float mz = fmaxf(z0, z1);
            float lse = mz + logf(expf(z0 - mz) + expf(z1 - mz));
            lp += (spin ? z1 : z0) - lse;
            __syncwarp();
            if (lane == 0) st_release(&g_rflags[mr], t);
        }
        out[b] = lp;
        return;
    }

    // ---------------- compute CTA ----------------
    const int m = bx >> 3, n = bx & 7;           // 16-row group, 64-col tile
    const int w = tid >> 5, lane = tid & 31;     // warp w handles cols 16w..16w+15
    const int n0 = n * N_TILE;
    const int q = lane >> 2, tg = lane & 3;

    // ldmatrix per-lane address bases
    const unsigned sA_s = (unsigned)__cvta_generic_to_shared(sA);
    const unsigned wt_s = (unsigned)__cvta_generic_to_shared(Wt);
    const unsigned aOff = ((lane >> 3) << 7) + ((lane & 7) << 4);      // A tile addr
    const unsigned brow = 16 * w + 8 * (lane >> 4) + (lane & 7);       // B tile row
    const unsigned bOff = wt_s + brow * (WT_STRIDE * 2) + (((lane >> 3) & 1) << 4);

    // ---- resident weight slice: Wt[j][k] = W[k][n0+j]
    for (int i = tid; i < N_TILE * 1024; i += 128) {
        int j = i >> 10, k = i & 1023;
        float wv = (k < U_) ? Wch[k * U_ + n0 + j] : Wcv[(k - U_) * U_ + n0 + j];
        Wt[j * WT_STRIDE + k] = __float2half_rn(wv);
    }
    if (tid < 64) {
        sWih[tid]       = Wih[n0 + tid];
        sWih[64 + tid]  = Wih[U_ + n0 + tid];
        sWiv[tid]       = Wiv[n0 + tid];
        sWiv[64 + tid]  = Wiv[U_ + n0 + tid];
        sBch[tid]       = bch[n0 + tid];
        sWo0[tid]       = Wout[(n0 + tid) * 2 + 0];
        sWo1[tid]       = Wout[(n0 + tid) * 2 + 1];
    }
    for (int i = tid; i < 4096; i += 128) {      // spins for this CTA's 16 rows
        int rl = i & 15, cell = i >> 4;
        sx[cell * 16 + rl] = (unsigned char)x[(16 * m + rl) * 256 + cell];
    }
    __syncthreads();

    int* myflags = g_flags + m * 8;

#pragma unroll 1
    for (int t = 1; t <= T_STEPS; ++t) {
        const int s = t - 1;
        const int r = s >> 4, p = s & 15;
        const int c  = (r & 1) ? (15 - p) : p;
        const int cp = (r & 1) ? (c + 1) : (c - 1);
        const bool has_h = (p > 0), has_v = (r > 0);

        const unsigned* cvsrc = pslab((r - 1) & 1, c) + (m << 12);
        const unsigned* hsrc  = pslab(r & 1, cp)      + (m << 12);

        // cv tile dep <= t-3 when p>=1: prefetch BEFORE waiting
        if (has_v && has_h) stage_copy16(sA_s, cvsrc, tid);

        if (t > 1) {
            if (tid < 8) {
                while (ld_acquire(myflags + tid) < t - 1) { }
            }
            if (tid == 8) {   // z-buffer back-pressure (almost never blocks)
                while (ld_acquire(&g_rflags[m >> 1]) < t - ZDEPTH) { }
            }
            __syncthreads();
        }

        // h tile is fresh (t-1): start its async copy right after the wait
        if (has_h) stage_copy16(sA_s + 16384, hsrc, tid);
        if (has_v && !has_h) stage_copy16(sA_s, cvsrc, tid);   // p==0: dep IS t-1

        float acc[2][4];
#pragma unroll
        for (int f = 0; f < 2; ++f)
            acc[f][0] = acc[f][1] = acc[f][2] = acc[f][3] = 0.f;

        if (has_v) {
            if (has_h) cp_wait<1>(); else cp_wait<0>();
            __syncthreads();
            gemm_ldsm(sA_s + aOff, bOff + 1024, acc);          // kofs=512 halves
        }
        if (has_h) {
            cp_wait<0>();
            __syncthreads();
            gemm_ldsm(sA_s + 16384 + aOff, bOff, acc);
        }

        // ---- epilogue
        int sLa = 0, sLb = 0, sUa = 0, sUb = 0;
        if (has_h) {
            sLa = sx[(r * 16 + cp) * 16 + q];
            sLb = sx[(r * 16 + cp) * 16 + q + 8];
        }
        if (has_v) {
            sUa = sx[((r - 1) * 16 + c) * 16 + q];
            sUb = sx[((r - 1) * 16 + c) * 16 + q + 8];
        }

        float z0a = 0.f, z1a = 0.f, z0b = 0.f, z1b = 0.f;
        unsigned* Pout = pslab(r & 1, c) + (m << 12) + ((4 * n + w) << 7) + lane;
#pragma unroll
        for (int f = 0; f < 2; ++f) {
            int u0 = 16 * w + 8 * f + 2 * tg;
            float v0 = acc[f][0] + sBch[u0];
            float v1 = acc[f][1] + sBch[u0 + 1];
            float v2 = acc[f][2] + sBch[u0];
            float v3 = acc[f][3] + sBch[u0 + 1];
            if (has_h) {
                v0 += sWih[sLa * 64 + u0]; v1 += sWih[sLa * 64 + u0 + 1];
                v2 += sWih[sLb * 64 + u0]; v3 += sWih[sLb * 64 + u0 + 1];
            }
            if (has_v) {
                v0 += sWiv[sUa * 64 + u0]; v1 += sWiv[sUa * 64 + u0 + 1];
                v2 += sWiv[sUb * 64 + u0]; v3 += sWiv[sUb * 64 + u0 + 1];
            }
            v0 = elu1(v0); v1 = elu1(v1); v2 = elu1(v2); v3 = elu1(v3);

            z0a += v0 * sWo0[u0] + v1 * sWo0[u0 + 1];
            z1a += v0 * sWo1[u0] + v1 * sWo1[u0 + 1];
            z0b += v2 * sWo0[u0] + v3 * sWo0[u0 + 1];
            z1b += v2 * sWo1[u0] + v3 * sWo1[u0 + 1];

            Pout[(2 * f) * 32]     = packh2(v0, v1);
            Pout[(2 * f + 1) * 32] = packh2(v2, v3);
        }
        // quad reduce over tg: lane tg==0 holds warp's 16-col sums
        z0a += __shfl_xor_sync(0xffffffffu, z0a, 1);
        z0a += __shfl_xor_sync(0xffffffffu, z0a, 2);
        z1a += __shfl_xor_sync(0xffffffffu, z1a, 1);
        z1a += __shfl_xor_sync(0xffffffffu, z1a, 2);
        z0b += __shfl_xor_sync(0xffffffffu, z0b, 1);
        z0b += __shfl_xor_sync(0xffffffffu, z0b, 2);
        z1b += __shfl_xor_sync(0xffffffffu, z1b, 1);
        z1b += __shfl_xor_sync(0xffffffffu, z1b, 2);
        if (tg == 0) {
            float2* zp = g_zpart + (((t & (ZDEPTH - 1)) * NTn + n) * 4 + w) * B_;
            int bA = 16 * m + q;
            zp[bA]     = make_float2(z0a, z1a);
            zp[bA + 8] = make_float2(z0b, z1b);
        }

        __syncthreads();
        if (tid == 0) st_release(&g_flags[bx], t);
    }
}

extern "C" void kernel_launch(void* const* d_in, const int* in_sizes, int n_in,
                              void* d_out, int out_size)
{
    (void)in_sizes; (void)n_in; (void)out_size;
    const int*   x    = (const int*)  d_in[0];
    const float* Wih  = (const float*)d_in[1];
    const float* Wiv  = (const float*)d_in[2];
    const float* Wch  = (const float*)d_in[3];
    const float* bch  = (const float*)d_in[4];
    const float* Wcv  = (const float*)d_in[5];
    const float* Wout = (const float*)d_in[6];
    const float* bout = (const float*)d_in[7];
    float* out = (float*)d_out;

    cudaFuncSetAttribute(rnn2d_main_kernel,
                         cudaFuncAttributeMaxDynamicSharedMemorySize, SM_TOTAL);

    rnn2d_init_kernel<<<1, 128>>>();
    rnn2d_main_kernel<<<NCOMP + NRED, 128, SM_TOTAL>>>(
        x, Wih, Wiv, Wch, bch, Wcv, Wout, bout, out);
}